// round 14
// baseline (speedup 1.0000x reference)
#include <cuda_runtime.h>
#include <cuda_fp16.h>
#include <cstdint>

#define NN 100000
#define NE 1600000
#define TOT (NE + NN)
#define HD 128
#define CHN 25088            // nodes per tail chunk (=196 gemm blocks x 128)
#define CHB 196              // gemm blocks per tail chunk

union H2U { unsigned int u; __half2 h; };
__device__ __forceinline__ unsigned int h2_to_u(__half2 h) { H2U c; c.h = h; return c.u; }
__device__ __forceinline__ __half2 u_to_h2(unsigned int u) { H2U c; c.u = u; return c.h; }

// ---------------- scratch (device globals; no allocation allowed) ------------
__device__ float4 g_hF[NN * 32];     // fp32 final h (input to GEMM2)
__device__ uint4  g_h16a[NN * 16];   // fp16 h0 (alpha term, written by gemm1)
__device__ uint4  g_h16b[NN * 16];   // fp16 ping
__device__ uint4  g_h16c[NN * 16];   // fp16 pong
__device__ int    g_cnt[NN];
__device__ int    g_fill[NN];
__device__ float  g_dinv[NN];
__device__ int    g_rowptr[NN + 1];
__device__ int2   g_ew[TOT];         // .x = src col, .y = float bits of 0.9*w
__device__ int    g_bsum[64];
__device__ int    g_is64;

// ---------------- init counters + edge dtype detection -----------------------
__global__ void initdet(const int* ei32) {
    int n = blockIdx.x * blockDim.x + threadIdx.x;
    if (n < NN) { g_cnt[n] = 1; g_fill[n] = 0; }
    if (blockIdx.x == 0 && threadIdx.x < 32) {
        int lane = threadIdx.x;
        int orv = 0;
        for (int i = lane; i < 1024; i += 32) orv |= ei32[2 * i + 1];
        #pragma unroll
        for (int off = 16; off; off >>= 1) orv |= __shfl_xor_sync(0xFFFFFFFFu, orv, off);
        if (lane == 0) g_is64 = (orv == 0) ? 1 : 0;
    }
}

__device__ __forceinline__ int edge_src(const void* ei, int e) {
    if (g_is64) return (int)((const long long*)ei)[e];
    return ((const int*)ei)[e];
}
__device__ __forceinline__ int edge_dst(const void* ei, int e) {
    if (g_is64) return (int)((const long long*)ei)[NE + e];
    return ((const int*)ei)[NE + e];
}

__global__ void hist(const void* __restrict__ ei) {
    int e = blockIdx.x * blockDim.x + threadIdx.x;
    if (e < NE) atomicAdd(&g_cnt[edge_dst(ei, e)], 1);
}

__global__ void scan1() {
    __shared__ int sh[256];
    int tid = threadIdx.x;
    int base = blockIdx.x * 2048 + tid * 8;
    int v[8];
    int s = 0;
    #pragma unroll
    for (int i = 0; i < 8; i++) {
        int idx = base + i;
        v[i] = (idx < NN) ? g_cnt[idx] : 0;
        if (idx < NN) g_dinv[idx] = rsqrtf((float)v[i]);
        s += v[i];
    }
    sh[tid] = s;
    __syncthreads();
    for (int off = 1; off < 256; off <<= 1) {
        int t = (tid >= off) ? sh[tid - off] : 0;
        __syncthreads();
        sh[tid] += t;
        __syncthreads();
    }
    int run = sh[tid] - s;
    #pragma unroll
    for (int i = 0; i < 8; i++) {
        int idx = base + i;
        if (idx < NN) g_rowptr[idx] = run;
        run += v[i];
    }
    if (tid == 255) g_bsum[blockIdx.x] = sh[255];
}

__global__ void scanfix() {
    __shared__ int soff;
    int idx = blockIdx.x * blockDim.x + threadIdx.x;
    int sblk = (blockIdx.x * 256) >> 11;
    if (threadIdx.x == 0) {
        int a = 0;
        for (int i = 0; i < sblk; i++) a += g_bsum[i];
        soff = a;
    }
    __syncthreads();
    if (idx < NN) g_rowptr[idx] += soff;
    if (idx == 0) g_rowptr[NN] = TOT;
}

__global__ void scatter(const void* __restrict__ ei) {
    int e = blockIdx.x * blockDim.x + threadIdx.x;
    if (e < NE) {
        int s = edge_src(ei, e);
        int d = edge_dst(ei, e);
        int pos = g_rowptr[d] + atomicAdd(&g_fill[d], 1);
        float ww = 0.9f * g_dinv[s] * g_dinv[d];
        g_ew[pos] = make_int2(s, __float_as_int(ww));
    } else if (e < TOT) {
        int n = e - NE;
        int pos = g_rowptr[n] + atomicAdd(&g_fill[n], 1);
        float di = g_dinv[n];
        g_ew[pos] = make_int2(n, __float_as_int(0.9f * di * di));
    }
}

// ---------------- 128-tile fp32 SGEMM ----------------------------------------
// mode 0: plain fp32 out.  mode 1: relu, write fp16 h0 to g_h16a only.
// blockOff: row-tile offset for chunked launches.
__global__ __launch_bounds__(256) void gemm128(
    const float* __restrict__ X, const float* __restrict__ Wm,
    const float* __restrict__ bias, float* __restrict__ out,
    int mode, int blockOff)
{
    __shared__ float As[128][33];
    __shared__ float Bs[32][128];

    int tid = threadIdx.x;
    int tx = tid & 15;
    int ty = tid >> 4;
    int rowBase = (blockIdx.x + blockOff) * 128;

    float acc[64];
    #pragma unroll
    for (int i = 0; i < 64; i++) acc[i] = 0.0f;

    for (int kc = 0; kc < 4; kc++) {
        #pragma unroll
        for (int l = 0; l < 4; l++) {
            int idx = tid + l * 256;
            int r  = idx >> 3;
            int kq = idx & 7;
            float4 v = make_float4(0.f, 0.f, 0.f, 0.f);
            int row = rowBase + r;
            if (row < NN)
                v = reinterpret_cast<const float4*>(X)[row * 32 + kc * 8 + kq];
            As[r][kq * 4 + 0] = v.x;
            As[r][kq * 4 + 1] = v.y;
            As[r][kq * 4 + 2] = v.z;
            As[r][kq * 4 + 3] = v.w;
        }
        #pragma unroll
        for (int l = 0; l < 4; l++) {
            int idx = tid + l * 256;
            int k  = idx >> 5;
            int cq = idx & 31;
            reinterpret_cast<float4*>(&Bs[k][0])[cq] =
                reinterpret_cast<const float4*>(Wm)[(kc * 32 + k) * 32 + cq];
        }
        __syncthreads();

        #pragma unroll
        for (int k = 0; k < 32; k++) {
            float b0[8], a0[8];
            *(float4*)&b0[0] = *(const float4*)&Bs[k][tx * 8];
            *(float4*)&b0[4] = *(const float4*)&Bs[k][tx * 8 + 4];
            #pragma unroll
            for (int i = 0; i < 8; i++) a0[i] = As[ty * 8 + i][k];
            #pragma unroll
            for (int i = 0; i < 8; i++)
                #pragma unroll
                for (int j = 0; j < 8; j++)
                    acc[i * 8 + j] = fmaf(a0[i], b0[j], acc[i * 8 + j]);
        }
        __syncthreads();
    }

    float bb[8];
    *(float4*)&bb[0] = *(const float4*)&bias[tx * 8];
    *(float4*)&bb[4] = *(const float4*)&bias[tx * 8 + 4];

    #pragma unroll
    for (int i = 0; i < 8; i++) {
        int row = rowBase + ty * 8 + i;
        if (row < NN) {
            float o[8];
            #pragma unroll
            for (int j = 0; j < 8; j++) o[j] = acc[i * 8 + j] + bb[j];
            if (mode) {
                #pragma unroll
                for (int j = 0; j < 8; j++) o[j] = fmaxf(o[j], 0.f);
                uint4 u;
                u.x = h2_to_u(__floats2half2_rn(o[0], o[1]));
                u.y = h2_to_u(__floats2half2_rn(o[2], o[3]));
                u.z = h2_to_u(__floats2half2_rn(o[4], o[5]));
                u.w = h2_to_u(__floats2half2_rn(o[6], o[7]));
                g_h16a[row * 16 + tx] = u;   // tx covers 8 cols = exactly 1 uint4
            } else {
                float4* op = reinterpret_cast<float4*>(out + row * HD + tx * 8);
                op[0] = *(float4*)&o[0];
                op[1] = *(float4*)&o[4];
            }
        }
    }
}

// ---------------- APPNP propagation: 16 threads/node, uint4 fp16 gathers -----
// t=0: in=g_h16a(h0). t>=1: in = (t odd ? g_h16b : g_h16c).
// out = (t odd ? g_h16c : g_h16b); t==9 writes fp32 g_hF.
// nodeLo/nodeHi: node range for chunked tail launches.
__global__ __launch_bounds__(256) void propagate(int t, int nodeLo, int nodeHi) {
    int idx = blockIdx.x * blockDim.x + threadIdx.x;
    int node = nodeLo + (idx >> 4);
    int lane = idx & 15;
    if (node >= nodeHi) return;

    const uint4* __restrict__ hin =
        (t == 0) ? g_h16a : ((t & 1) ? g_h16b : g_h16c);
    uint4* __restrict__ hout = (t & 1) ? g_h16c : g_h16b;

    int beg = g_rowptr[node];
    int end = g_rowptr[node + 1];

    float a0 = 0.f, a1 = 0.f, a2 = 0.f, a3 = 0.f;
    float a4 = 0.f, a5 = 0.f, a6 = 0.f, a7 = 0.f;
    #pragma unroll 4
    for (int e = beg; e < end; e++) {
        int2 ew = __ldg(&g_ew[e]);
        float ww = __int_as_float(ew.y);
        uint4 hv = __ldg(&hin[ew.x * 16 + lane]);
        float2 f0 = __half22float2(u_to_h2(hv.x));
        float2 f1 = __half22float2(u_to_h2(hv.y));
        float2 f2 = __half22float2(u_to_h2(hv.z));
        float2 f3 = __half22float2(u_to_h2(hv.w));
        a0 = fmaf(ww, f0.x, a0); a1 = fmaf(ww, f0.y, a1);
        a2 = fmaf(ww, f1.x, a2); a3 = fmaf(ww, f1.y, a3);
        a4 = fmaf(ww, f2.x, a4); a5 = fmaf(ww, f2.y, a5);
        a6 = fmaf(ww, f3.x, a6); a7 = fmaf(ww, f3.y, a7);
    }

    uint4 zv = __ldg(&g_h16a[node * 16 + lane]);
    float2 z0 = __half22float2(u_to_h2(zv.x));
    float2 z1 = __half22float2(u_to_h2(zv.y));
    float2 z2 = __half22float2(u_to_h2(zv.z));
    float2 z3 = __half22float2(u_to_h2(zv.w));
    float o0 = a0 + 0.1f * z0.x, o1 = a1 + 0.1f * z0.y;
    float o2 = a2 + 0.1f * z1.x, o3 = a3 + 0.1f * z1.y;
    float o4 = a4 + 0.1f * z2.x, o5 = a5 + 0.1f * z2.y;
    float o6 = a6 + 0.1f * z3.x, o7 = a7 + 0.1f * z3.y;

    if (t == 9) {
        g_hF[node * 32 + lane * 2 + 0] = make_float4(o0, o1, o2, o3);
        g_hF[node * 32 + lane * 2 + 1] = make_float4(o4, o5, o6, o7);
    } else {
        uint4 u;
        u.x = h2_to_u(__floats2half2_rn(o0, o1));
        u.y = h2_to_u(__floats2half2_rn(o2, o3));
        u.z = h2_to_u(__floats2half2_rn(o4, o5));
        u.w = h2_to_u(__floats2half2_rn(o6, o7));
        hout[node * 16 + lane] = u;
    }
}

// ---------------- launch ------------------------------------------------------
static cudaStream_t s_gemm = nullptr;
static cudaEvent_t  s_fork = nullptr, s_join = nullptr, s_join2 = nullptr;
static cudaEvent_t  s_ch[4] = {nullptr, nullptr, nullptr, nullptr};

extern "C" void kernel_launch(void* const* d_in, const int* in_sizes, int n_in,
                              void* d_out, int out_size) {
    const float* x  = (const float*)d_in[0];
    const void*  ei = d_in[1];
    const float* W1 = (const float*)d_in[2];
    const float* b1 = (const float*)d_in[3];
    const float* W2 = (const float*)d_in[4];
    const float* b2 = (const float*)d_in[5];
    float* out = (float*)d_out;

    void* p_hF = nullptr;
    cudaGetSymbolAddress(&p_hF, g_hF);

    // one-time host resource setup (first call is the uncaptured correctness run)
    if (!s_gemm) {
        cudaStreamCreateWithFlags(&s_gemm, cudaStreamNonBlocking);
        cudaEventCreateWithFlags(&s_fork, cudaEventDisableTiming);
        cudaEventCreateWithFlags(&s_join, cudaEventDisableTiming);
        cudaEventCreateWithFlags(&s_join2, cudaEventDisableTiming);
        for (int i = 0; i < 4; i++)
            cudaEventCreateWithFlags(&s_ch[i], cudaEventDisableTiming);
    }

    const int T = 256;

    // fork: gemm1 runs concurrently with the CSR build chain
    cudaEventRecord(s_fork, 0);
    cudaStreamWaitEvent(s_gemm, s_fork, 0);
    gemm128<<<(NN + 127) / 128, 256, 0, s_gemm>>>(x, W1, b1, nullptr, 1, 0);
    cudaEventRecord(s_join, s_gemm);

    initdet<<<(NN + T - 1) / T, T>>>((const int*)ei);
    hist<<<(NE + T - 1) / T, T>>>(ei);
    scan1<<<(NN + 2047) / 2048, 256>>>();
    scanfix<<<(NN + T - 1) / T, T>>>();
    scatter<<<(TOT + T - 1) / T, T>>>(ei);

    // join before propagation (needs both h0 and CSR)
    cudaStreamWaitEvent(0, s_join, 0);

    for (int t = 0; t < 9; t++)
        propagate<<<(NN * 16 + T - 1) / T, T>>>(t, 0, NN);

    // tail pipeline: propagate t=9 in 4 node chunks, each releasing its gemm2 chunk
    for (int c = 0; c < 4; c++) {
        int lo = c * CHN;
        int hi = (c == 3) ? NN : (c + 1) * CHN;
        int nodes = hi - lo;
        propagate<<<(nodes * 16 + T - 1) / T, T>>>(9, lo, hi);
        cudaEventRecord(s_ch[c], 0);
        cudaStreamWaitEvent(s_gemm, s_ch[c], 0);
        int blocks = (c == 3) ? (782 - 3 * CHB) : CHB;
        gemm128<<<blocks, 256, 0, s_gemm>>>((const float*)p_hF, W2, b2, out, 0, c * CHB);
    }
    cudaEventRecord(s_join2, s_gemm);
    cudaStreamWaitEvent(0, s_join2, 0);
}

// round 15
// speedup vs baseline: 1.2347x; 1.2347x over previous
#include <cuda_runtime.h>
#include <cuda_fp16.h>
#include <cstdint>

#define NN 100000
#define NE 1600000
#define TOT (NE + NN)
#define HD 128

union H2U { unsigned int u; __half2 h; };
__device__ __forceinline__ unsigned int h2_to_u(__half2 h) { H2U c; c.h = h; return c.u; }
__device__ __forceinline__ __half2 u_to_h2(unsigned int u) { H2U c; c.u = u; return c.h; }

// ---------------- scratch (device globals; no allocation allowed) ------------
__device__ uint4  g_h16a[NN * 16];   // fp16 h0 (alpha term, written by gemm1)
__device__ uint4  g_h16b[NN * 16];   // fp16 ping
__device__ uint4  g_h16c[NN * 16];   // fp16 pong (final h lands here after t=9)
__device__ int    g_cnt[NN];
__device__ int    g_fill[NN];
__device__ float  g_dinv[NN];
__device__ int    g_rowptr[NN + 1];
__device__ int2   g_ew[TOT];         // .x = src col, .y = float bits of 0.9*w
__device__ int    g_bsum[64];
__device__ int    g_is64;

// ---------------- init counters + edge dtype detection -----------------------
__global__ void initdet(const int* ei32) {
    int n = blockIdx.x * blockDim.x + threadIdx.x;
    if (n < NN) { g_cnt[n] = 1; g_fill[n] = 0; }
    if (blockIdx.x == 0 && threadIdx.x < 32) {
        int lane = threadIdx.x;
        int orv = 0;
        for (int i = lane; i < 1024; i += 32) orv |= ei32[2 * i + 1];
        #pragma unroll
        for (int off = 16; off; off >>= 1) orv |= __shfl_xor_sync(0xFFFFFFFFu, orv, off);
        if (lane == 0) g_is64 = (orv == 0) ? 1 : 0;
    }
}

__device__ __forceinline__ int edge_src(const void* ei, int e) {
    if (g_is64) return (int)((const long long*)ei)[e];
    return ((const int*)ei)[e];
}
__device__ __forceinline__ int edge_dst(const void* ei, int e) {
    if (g_is64) return (int)((const long long*)ei)[NE + e];
    return ((const int*)ei)[NE + e];
}

__global__ void hist(const void* __restrict__ ei) {
    int e = blockIdx.x * blockDim.x + threadIdx.x;
    if (e < NE) atomicAdd(&g_cnt[edge_dst(ei, e)], 1);
}

__global__ void scan1() {
    __shared__ int sh[256];
    int tid = threadIdx.x;
    int base = blockIdx.x * 2048 + tid * 8;
    int v[8];
    int s = 0;
    #pragma unroll
    for (int i = 0; i < 8; i++) {
        int idx = base + i;
        v[i] = (idx < NN) ? g_cnt[idx] : 0;
        if (idx < NN) g_dinv[idx] = rsqrtf((float)v[i]);
        s += v[i];
    }
    sh[tid] = s;
    __syncthreads();
    for (int off = 1; off < 256; off <<= 1) {
        int t = (tid >= off) ? sh[tid - off] : 0;
        __syncthreads();
        sh[tid] += t;
        __syncthreads();
    }
    int run = sh[tid] - s;
    #pragma unroll
    for (int i = 0; i < 8; i++) {
        int idx = base + i;
        if (idx < NN) g_rowptr[idx] = run;
        run += v[i];
    }
    if (tid == 255) g_bsum[blockIdx.x] = sh[255];
}

__global__ void scanfix() {
    __shared__ int soff;
    int idx = blockIdx.x * blockDim.x + threadIdx.x;
    int sblk = (blockIdx.x * 256) >> 11;
    if (threadIdx.x == 0) {
        int a = 0;
        for (int i = 0; i < sblk; i++) a += g_bsum[i];
        soff = a;
    }
    __syncthreads();
    if (idx < NN) g_rowptr[idx] += soff;
    if (idx == 0) g_rowptr[NN] = TOT;
}

__global__ void scatter(const void* __restrict__ ei) {
    int e = blockIdx.x * blockDim.x + threadIdx.x;
    if (e < NE) {
        int s = edge_src(ei, e);
        int d = edge_dst(ei, e);
        int pos = g_rowptr[d] + atomicAdd(&g_fill[d], 1);
        float ww = 0.9f * g_dinv[s] * g_dinv[d];
        g_ew[pos] = make_int2(s, __float_as_int(ww));
    } else if (e < TOT) {
        int n = e - NE;
        int pos = g_rowptr[n] + atomicAdd(&g_fill[n], 1);
        float di = g_dinv[n];
        g_ew[pos] = make_int2(n, __float_as_int(0.9f * di * di));
    }
}

// ---------------- fp16 HMMA GEMM: D = X @ W + b ------------------------------
// CTA 128x128 tile, 8 warps (4m x 2n), warp 32x64, mma.m16n8k16.f16, fp32 acc.
// inhalf: X is fp16 uint4 rows (g_h16*) vs fp32. mode 1: relu + fp16 h0 store.
#define LDK 136
#define SM_A 0
#define SM_B (128 * LDK * 2)
#define SM_SB (2 * 128 * LDK * 2)
#define SMEMH (SM_SB + 512)

__device__ __forceinline__ void mma_f16(float* d, unsigned a0, unsigned a1,
                                        unsigned a2, unsigned a3,
                                        unsigned b0, unsigned b1) {
    asm volatile("mma.sync.aligned.m16n8k16.row.col.f32.f16.f16.f32 "
                 "{%0,%1,%2,%3}, {%4,%5,%6,%7}, {%8,%9}, {%0,%1,%2,%3};"
                 : "+f"(d[0]), "+f"(d[1]), "+f"(d[2]), "+f"(d[3])
                 : "r"(a0), "r"(a1), "r"(a2), "r"(a3), "r"(b0), "r"(b1));
}

__global__ __launch_bounds__(256) void gemm_h(
    const void* __restrict__ Xin, const float* __restrict__ Wm,
    const float* __restrict__ bias, float* __restrict__ out,
    int mode, int inhalf)
{
    extern __shared__ char smem[];
    __half* Ah = (__half*)(smem + SM_A);
    __half* Bh = (__half*)(smem + SM_B);
    float* sb = (float*)(smem + SM_SB);

    int tid = threadIdx.x;
    int wid = tid >> 5;
    int lane = tid & 31;
    int rowBase = blockIdx.x * 128;

    if (tid < 128) sb[tid] = bias[tid];

    // ---- load A (128 rows x 128 k halves) ----
    if (inhalf) {
        // rows are already fp16: 16 uint4 per row, straight copy
        #pragma unroll
        for (int l = 0; l < 8; l++) {
            int idx = tid + l * 256;        // 0..2047
            int r = idx >> 4;
            int q = idx & 15;
            uint4 v = make_uint4(0, 0, 0, 0);
            if (rowBase + r < NN)
                v = reinterpret_cast<const uint4*>(Xin)[(rowBase + r) * 16 + q];
            *(uint4*)&Ah[r * LDK + q * 8] = v;
        }
    } else {
        #pragma unroll
        for (int l = 0; l < 16; l++) {
            int idx = tid + l * 256;        // 0..4095
            int r = idx >> 5;
            int kq = idx & 31;
            float4 v = make_float4(0.f, 0.f, 0.f, 0.f);
            if (rowBase + r < NN)
                v = reinterpret_cast<const float4*>(Xin)[(rowBase + r) * 32 + kq];
            uint2 u;
            u.x = h2_to_u(__floats2half2_rn(v.x, v.y));
            u.y = h2_to_u(__floats2half2_rn(v.z, v.w));
            *(uint2*)&Ah[r * LDK + kq * 4] = u;
        }
    }
    // ---- load + transpose + convert W: Wm[k][n] fp32 -> Bh[n][k] fp16 ----
    #pragma unroll
    for (int l = 0; l < 16; l++) {
        int idx = tid + l * 256;            // 0..4095
        int k = idx >> 5;
        int nq = idx & 31;
        float4 v = reinterpret_cast<const float4*>(Wm)[k * 32 + nq];
        Bh[(nq * 4 + 0) * LDK + k] = __float2half_rn(v.x);
        Bh[(nq * 4 + 1) * LDK + k] = __float2half_rn(v.y);
        Bh[(nq * 4 + 2) * LDK + k] = __float2half_rn(v.z);
        Bh[(nq * 4 + 3) * LDK + k] = __float2half_rn(v.w);
    }
    __syncthreads();

    int wm = wid & 3;          // row group: wm*32
    int wn = wid >> 2;         // col group: wn*64
    int qr = lane >> 2;        // 0..7
    int qc = (lane & 3) * 2;   // 0,2,4,6

    float acc[2][8][4];
    #pragma unroll
    for (int mt = 0; mt < 2; mt++)
        #pragma unroll
        for (int nt = 0; nt < 8; nt++)
            #pragma unroll
            for (int c = 0; c < 4; c++) acc[mt][nt][c] = 0.f;

    #pragma unroll
    for (int ks = 0; ks < 8; ks++) {
        int k0 = ks * 16;
        unsigned a[2][4], b[8][2];
        #pragma unroll
        for (int mt = 0; mt < 2; mt++) {
            int r = wm * 32 + mt * 16 + qr;
            const __half* ap = Ah + r * LDK + k0 + qc;
            a[mt][0] = *(const unsigned*)(ap);
            a[mt][1] = *(const unsigned*)(ap + 8 * LDK);
            a[mt][2] = *(const unsigned*)(ap + 8);
            a[mt][3] = *(const unsigned*)(ap + 8 * LDK + 8);
        }
        #pragma unroll
        for (int nt = 0; nt < 8; nt++) {
            int n = wn * 64 + nt * 8 + qr;
            const __half* bp = Bh + n * LDK + k0 + qc;
            b[nt][0] = *(const unsigned*)(bp);
            b[nt][1] = *(const unsigned*)(bp + 8);
        }
        #pragma unroll
        for (int mt = 0; mt < 2; mt++)
            #pragma unroll
            for (int nt = 0; nt < 8; nt++)
                mma_f16(acc[mt][nt], a[mt][0], a[mt][1], a[mt][2], a[mt][3],
                        b[nt][0], b[nt][1]);
    }

    // ---- epilogue ----
    #pragma unroll
    for (int mt = 0; mt < 2; mt++) {
        #pragma unroll
        for (int nt = 0; nt < 8; nt++) {
            int c = wn * 64 + nt * 8 + qc;
            float bx = sb[c], by = sb[c + 1];
            int r0 = rowBase + wm * 32 + mt * 16 + qr;
            int r1 = r0 + 8;
            float d0 = acc[mt][nt][0] + bx, d1 = acc[mt][nt][1] + by;
            float d2 = acc[mt][nt][2] + bx, d3 = acc[mt][nt][3] + by;
            if (mode) {
                d0 = fmaxf(d0, 0.f); d1 = fmaxf(d1, 0.f);
                d2 = fmaxf(d2, 0.f); d3 = fmaxf(d3, 0.f);
                unsigned p0 = h2_to_u(__floats2half2_rn(d0, d1));
                unsigned p1 = h2_to_u(__floats2half2_rn(d2, d3));
                if (r0 < NN) ((unsigned*)g_h16a)[r0 * 64 + (c >> 1)] = p0;
                if (r1 < NN) ((unsigned*)g_h16a)[r1 * 64 + (c >> 1)] = p1;
            } else {
                if (r0 < NN) *(float2*)(out + r0 * HD + c) = make_float2(d0, d1);
                if (r1 < NN) *(float2*)(out + r1 * HD + c) = make_float2(d2, d3);
            }
        }
    }
}

// ---------------- APPNP propagation: 16 threads/node, uint4 fp16 gathers -----
// t=0: in=g_h16a(h0). t>=1: in = (t odd ? g_h16b : g_h16c).
// out = (t odd ? g_h16c : g_h16b). alpha term always from g_h16a.
// t=9 (odd) leaves the final h in g_h16c.
__global__ __launch_bounds__(256) void propagate(int t) {
    int idx = blockIdx.x * blockDim.x + threadIdx.x;
    int node = idx >> 4;
    int lane = idx & 15;
    if (node >= NN) return;

    const uint4* __restrict__ hin =
        (t == 0) ? g_h16a : ((t & 1) ? g_h16b : g_h16c);
    uint4* __restrict__ hout = (t & 1) ? g_h16c : g_h16b;

    int beg = g_rowptr[node];
    int end = g_rowptr[node + 1];

    float a0 = 0.f, a1 = 0.f, a2 = 0.f, a3 = 0.f;
    float a4 = 0.f, a5 = 0.f, a6 = 0.f, a7 = 0.f;
    #pragma unroll 4
    for (int e = beg; e < end; e++) {
        int2 ew = __ldg(&g_ew[e]);
        float ww = __int_as_float(ew.y);
        uint4 hv = __ldg(&hin[ew.x * 16 + lane]);
        float2 f0 = __half22float2(u_to_h2(hv.x));
        float2 f1 = __half22float2(u_to_h2(hv.y));
        float2 f2 = __half22float2(u_to_h2(hv.z));
        float2 f3 = __half22float2(u_to_h2(hv.w));
        a0 = fmaf(ww, f0.x, a0); a1 = fmaf(ww, f0.y, a1);
        a2 = fmaf(ww, f1.x, a2); a3 = fmaf(ww, f1.y, a3);
        a4 = fmaf(ww, f2.x, a4); a5 = fmaf(ww, f2.y, a5);
        a6 = fmaf(ww, f3.x, a6); a7 = fmaf(ww, f3.y, a7);
    }

    uint4 zv = __ldg(&g_h16a[node * 16 + lane]);
    float2 z0 = __half22float2(u_to_h2(zv.x));
    float2 z1 = __half22float2(u_to_h2(zv.y));
    float2 z2 = __half22float2(u_to_h2(zv.z));
    float2 z3 = __half22float2(u_to_h2(zv.w));
    float o0 = a0 + 0.1f * z0.x, o1 = a1 + 0.1f * z0.y;
    float o2 = a2 + 0.1f * z1.x, o3 = a3 + 0.1f * z1.y;
    float o4 = a4 + 0.1f * z2.x, o5 = a5 + 0.1f * z2.y;
    float o6 = a6 + 0.1f * z3.x, o7 = a7 + 0.1f * z3.y;

    uint4 u;
    u.x = h2_to_u(__floats2half2_rn(o0, o1));
    u.y = h2_to_u(__floats2half2_rn(o2, o3));
    u.z = h2_to_u(__floats2half2_rn(o4, o5));
    u.w = h2_to_u(__floats2half2_rn(o6, o7));
    hout[node * 16 + lane] = u;
}

// ---------------- launch ------------------------------------------------------
static cudaStream_t s_gemm = nullptr;
static cudaEvent_t  s_fork = nullptr, s_join = nullptr;

extern "C" void kernel_launch(void* const* d_in, const int* in_sizes, int n_in,
                              void* d_out, int out_size) {
    const float* x  = (const float*)d_in[0];
    const void*  ei = d_in[1];
    const float* W1 = (const float*)d_in[2];
    const float* b1 = (const float*)d_in[3];
    const float* W2 = (const float*)d_in[4];
    const float* b2 = (const float*)d_in[5];
    float* out = (float*)d_out;

    void* p_hc = nullptr;
    cudaGetSymbolAddress(&p_hc, g_h16c);

    if (!s_gemm) {
        cudaStreamCreateWithFlags(&s_gemm, cudaStreamNonBlocking);
        cudaEventCreateWithFlags(&s_fork, cudaEventDisableTiming);
        cudaEventCreateWithFlags(&s_join, cudaEventDisableTiming);
        cudaFuncSetAttribute(gemm_h, cudaFuncAttributeMaxDynamicSharedMemorySize, SMEMH);
    }

    const int T = 256;

    // fork: gemm1 runs concurrently with the CSR build chain
    cudaEventRecord(s_fork, 0);
    cudaStreamWaitEvent(s_gemm, s_fork, 0);
    gemm_h<<<(NN + 127) / 128, 256, SMEMH, s_gemm>>>(x, W1, b1, nullptr, 1, 0);
    cudaEventRecord(s_join, s_gemm);

    initdet<<<(NN + T - 1) / T, T>>>((const int*)ei);
    hist<<<(NE + T - 1) / T, T>>>(ei);
    scan1<<<(NN + 2047) / 2048, 256>>>();
    scanfix<<<(NN + T - 1) / T, T>>>();
    scatter<<<(TOT + T - 1) / T, T>>>(ei);

    cudaStreamWaitEvent(0, s_join, 0);

    for (int t = 0; t < 10; t++)
        propagate<<<(NN * 16 + T - 1) / T, T>>>(t);

    // final h (fp16) is in g_h16c
    gemm_h<<<(NN + 127) / 128, 256, SMEMH>>>(p_hc, W2, b2, out, 0, 1);
}